// round 3
// baseline (speedup 1.0000x reference)
#include <cuda_runtime.h>

typedef unsigned long long u64;

#define BC 8
#define NB 2048
#define NG (NB/BC)
#define VMAXD 128

// ---------------- device scratch (no allocations allowed) ----------------
__device__ float g_Wih1g[15*1024];
__device__ float g_Whh1g[256*1024];
__device__ float g_b1c[1024];
__device__ float g_Wih2g[256*1024];
__device__ float g_Whh2g[256*1024];
__device__ float g_b2c[1024];
__device__ float g_W1T[256*1024];
__device__ float g_W2T[1024*1024];
__device__ float g_W3T[1024*512];
__device__ float g_W4T[512*256];
__device__ float g_henc[NB*256];
__device__ float g_x1[NB*1024];
__device__ float g_x2[NB*1024];
__device__ float g_x3[NB*512];
__device__ float g_x4[NB*256];
__device__ float g_decin[NB*1024];
__device__ int   g_hist[129];
__device__ int   g_start[129];
__device__ int   g_cur[129];
__device__ int   g_order[NB];

// ---------------- f32x2 helpers (sm_103a packed fp32) ----------------
__device__ __forceinline__ u64 pk2(float x, float y){
    u64 r; asm("mov.b64 %0,{%1,%2};" : "=l"(r) : "f"(x), "f"(y)); return r;
}
__device__ __forceinline__ float2 upk2(u64 v){
    float2 r; asm("mov.b64 {%0,%1},%2;" : "=f"(r.x), "=f"(r.y) : "l"(v)); return r;
}
__device__ __forceinline__ void fma2(u64& d, u64 a, u64 b){
    asm("fma.rn.f32x2 %0,%1,%2,%0;" : "+l"(d) : "l"(a), "l"(b));
}

__device__ __forceinline__ float sigf(float x){ return 1.0f/(1.0f + __expf(-x)); }
__device__ __forceinline__ float tanhfast(float x){ return 2.0f*sigf(2.0f*x) - 1.0f; }

// ---------------- weight prep ----------------
// gate-interleaved transpose: dst[k*1024 + j*4+g] = W[(g*256+j)*K + k]
__global__ void k_prep_gates(const float* __restrict__ Whh1,
                             const float* __restrict__ Wih2,
                             const float* __restrict__ Whh2){
    int idx = blockIdx.x*blockDim.x + threadIdx.x;   // 3*262144
    int m = idx >> 18;
    int r = idx & 262143;
    int k = r >> 10; int n = r & 1023; int jj = n >> 2, g = n & 3;
    int src = (g*256 + jj)*256 + k;
    if (m == 0)      g_Whh1g[r] = Whh1[src];
    else if (m == 1) g_Wih2g[r] = Wih2[src];
    else             g_Whh2g[r] = Whh2[src];
}

__global__ void k_prep_small(const float* __restrict__ Wih1,
                             const float* __restrict__ bih1, const float* __restrict__ bhh1,
                             const float* __restrict__ bih2, const float* __restrict__ bhh2){
    int idx = blockIdx.x*blockDim.x + threadIdx.x;   // 17408
    if (idx < 15360){
        int k = idx >> 10, n = idx & 1023, jj = n >> 2, g = n & 3;
        g_Wih1g[idx] = Wih1[(g*256 + jj)*15 + k];
    } else if (idx < 16384){
        int n = idx - 15360; int jj = n >> 2, g = n & 3;
        g_b1c[n] = bih1[g*256 + jj] + bhh1[g*256 + jj];
    } else if (idx < 17408){
        int n = idx - 16384; int jj = n >> 2, g = n & 3;
        g_b2c[n] = bih2[g*256 + jj] + bhh2[g*256 + jj];
    }
}

__global__ void k_prep_T(const float* __restrict__ W1, const float* __restrict__ W2,
                         const float* __restrict__ W3, const float* __restrict__ W4){
    int idx = blockIdx.x*blockDim.x + threadIdx.x;   // 1966080 total
    if (idx < 262144){
        int k = idx >> 10, n = idx & 1023; g_W1T[idx] = W1[n*256 + k];
    } else if (idx < 1310720){
        int r = idx - 262144; int k = r >> 10, n = r & 1023; g_W2T[r] = W2[n*1024 + k];
    } else if (idx < 1835008){
        int r = idx - 1310720; int k = r >> 9, n = r & 511; g_W3T[r] = W3[n*1024 + k];
    } else if (idx < 1966080){
        int r = idx - 1835008; int k = r >> 8, n = r & 255; g_W4T[r] = W4[n*512 + k];
    }
}

// ---------------- length sort (descending counting sort) ----------------
__global__ void k_sort_init(){ int t = threadIdx.x; if (t < 129){ g_hist[t] = 0; g_cur[t] = 0; } }
__global__ void k_sort_hist(const int* __restrict__ lengths){
    int b = blockIdx.x*blockDim.x + threadIdx.x;
    if (b < NB) atomicAdd(&g_hist[lengths[b]], 1);
}
__global__ void k_sort_scan(){
    int run = 0;
    for (int l = 128; l >= 1; l--){ g_start[l] = run; run += g_hist[l]; }
}
__global__ void k_sort_scatter(const int* __restrict__ lengths){
    int b = blockIdx.x*blockDim.x + threadIdx.x;
    if (b < NB){
        int l = lengths[b];
        int p = g_start[l] + atomicAdd(&g_cur[l], 1);
        g_order[p] = b;
    }
}

// ---------------- encoder LSTM (persistent, batch-parallel) ----------------
__global__ __launch_bounds__(256, 2)
void k_encoder(const float* __restrict__ state, const int* __restrict__ lengths){
    __shared__ int s_b[BC]; __shared__ int s_len[BC]; __shared__ int s_max;
    __shared__ __align__(16) float h_s[256*10];    // [k][pairs], stride 10
    __shared__ __align__(16) float x_s[2][16*8];   // [buf][e][i]
    const int tid = threadIdx.x;
    if (tid < BC){ int b = g_order[blockIdx.x*BC + tid]; s_b[tid] = b; s_len[tid] = lengths[b]; }
    for (int i = tid; i < 2560; i += 256) h_s[i] = 0.0f;
    __syncthreads();
    if (tid == 0){
        int m = 1;
        #pragma unroll
        for (int i = 0; i < BC; i++) m = max(m, s_len[i]);
        s_max = m;
    }
    if (tid < 120){ int i = tid/15, e = tid - 15*i; x_s[0][e*8 + i] = state[(s_b[i]*VMAXD + 0)*15 + e]; }
    __syncthreads();

    const int j = tid;
    const float4 bv = *(const float4*)(g_b1c + 4*j);
    const u64 bi0 = pk2(bv.x, bv.x), bi1 = pk2(bv.y, bv.y), bi2 = pk2(bv.z, bv.z), bi3 = pk2(bv.w, bv.w);
    float cr[BC];
    #pragma unroll
    for (int i = 0; i < BC; i++) cr[i] = 0.0f;

    const int T = s_max;
    for (int t = 0; t < T; t++){
        u64 acc[4][4];
        #pragma unroll
        for (int bp = 0; bp < 4; bp++){ acc[bp][0]=bi0; acc[bp][1]=bi1; acc[bp][2]=bi2; acc[bp][3]=bi3; }

        const float* xs = x_s[t & 1];
        #pragma unroll
        for (int k = 0; k < 15; k++){
            float4 w = *(const float4*)(g_Wih1g + (k<<10) + (j<<2));
            u64 w0 = pk2(w.x,w.x), w1 = pk2(w.y,w.y), w2 = pk2(w.z,w.z), w3 = pk2(w.w,w.w);
            #pragma unroll
            for (int bp = 0; bp < 4; bp++){
                u64 xp = *(const u64*)(xs + (k<<3) + 2*bp);
                fma2(acc[bp][0], w0, xp); fma2(acc[bp][1], w1, xp);
                fma2(acc[bp][2], w2, xp); fma2(acc[bp][3], w3, xp);
            }
        }
        #pragma unroll 4
        for (int k = 0; k < 256; k++){
            float4 w = *(const float4*)(g_Whh1g + (k<<10) + (j<<2));
            u64 w0 = pk2(w.x,w.x), w1 = pk2(w.y,w.y), w2 = pk2(w.z,w.z), w3 = pk2(w.w,w.w);
            const float* hr = h_s + k*10;
            #pragma unroll
            for (int bp = 0; bp < 4; bp++){
                u64 hp = *(const u64*)(hr + 2*bp);
                fma2(acc[bp][0], w0, hp); fma2(acc[bp][1], w1, hp);
                fma2(acc[bp][2], w2, hp); fma2(acc[bp][3], w3, hp);
            }
        }
        __syncthreads();   // all h_s reads complete before writes

        if (tid < 120 && t + 1 < T){
            int i = tid/15, e = tid - 15*i;
            x_s[(t+1)&1][e*8 + i] = state[(s_b[i]*VMAXD + (t+1))*15 + e];
        }
        #pragma unroll
        for (int bp = 0; bp < 4; bp++){
            float2 gi = upk2(acc[bp][0]), gf = upk2(acc[bp][1]);
            float2 gg = upk2(acc[bp][2]), go = upk2(acc[bp][3]);
            int b = 2*bp;
            if (t < s_len[b]){
                float cn = sigf(gf.x)*cr[b] + sigf(gi.x)*tanhfast(gg.x);
                cr[b] = cn; h_s[j*10 + b] = sigf(go.x)*tanhfast(cn);
            }
            b++;
            if (t < s_len[b]){
                float cn = sigf(gf.y)*cr[b] + sigf(gi.y)*tanhfast(gg.y);
                cr[b] = cn; h_s[j*10 + b] = sigf(go.y)*tanhfast(cn);
            }
        }
        __syncthreads();   // h_s / x_s ready for next step
    }
    #pragma unroll
    for (int i = 0; i < BC; i++) g_henc[s_b[i]*256 + j] = h_s[j*10 + i];
}

// ---------------- row GEMM: C = act(A @ W^T + bias), 8 rows / CTA ----------------
__global__ __launch_bounds__(256, 2)
void k_rowgemm(int layer, const float* __restrict__ bias_in){
    const float *A, *W; float* C; int K, N; bool dorelu = true; const float* bias = bias_in;
    if      (layer == 0){ A = g_henc; W = g_W1T;   C = g_x1;    K = 256;  N = 1024; }
    else if (layer == 1){ A = g_x1;   W = g_W2T;   C = g_x2;    K = 1024; N = 1024; }
    else if (layer == 2){ A = g_x2;   W = g_W3T;   C = g_x3;    K = 1024; N = 512;  }
    else if (layer == 3){ A = g_x3;   W = g_W4T;   C = g_x4;    K = 512;  N = 256;  }
    else               { A = g_x4;   W = g_Wih2g; C = g_decin; K = 256;  N = 1024; dorelu = false; bias = g_b2c; }

    __shared__ __align__(16) float A_s[1024*8];
    const int tid = threadIdx.x;
    const int row0 = blockIdx.x * 8;
    for (int idx = tid; idx < 8*K; idx += 256){
        int i = idx / K, k = idx - i*K;
        A_s[k*8 + i] = A[(row0 + i)*K + k];
    }
    __syncthreads();

    const int j = tid;
    if (4*j < N){
        float4 bvv = *(const float4*)(bias + 4*j);
        u64 acc[4][4];
        u64 b0 = pk2(bvv.x,bvv.x), b1 = pk2(bvv.y,bvv.y), b2 = pk2(bvv.z,bvv.z), b3 = pk2(bvv.w,bvv.w);
        #pragma unroll
        for (int bp = 0; bp < 4; bp++){ acc[bp][0]=b0; acc[bp][1]=b1; acc[bp][2]=b2; acc[bp][3]=b3; }

        #pragma unroll 4
        for (int k = 0; k < K; k++){
            float4 w = *(const float4*)(W + k*N + 4*j);
            u64 w0 = pk2(w.x,w.x), w1 = pk2(w.y,w.y), w2 = pk2(w.z,w.z), w3 = pk2(w.w,w.w);
            const float* ar = A_s + k*8;
            #pragma unroll
            for (int bp = 0; bp < 4; bp++){
                u64 ap = *(const u64*)(ar + 2*bp);
                fma2(acc[bp][0], w0, ap); fma2(acc[bp][1], w1, ap);
                fma2(acc[bp][2], w2, ap); fma2(acc[bp][3], w3, ap);
            }
        }
        #pragma unroll
        for (int bp = 0; bp < 4; bp++){
            float2 v0 = upk2(acc[bp][0]), v1 = upk2(acc[bp][1]);
            float2 v2 = upk2(acc[bp][2]), v3 = upk2(acc[bp][3]);
            float4 r0 = make_float4(v0.x, v1.x, v2.x, v3.x);
            float4 r1 = make_float4(v0.y, v1.y, v2.y, v3.y);
            if (dorelu){
                r0.x = fmaxf(r0.x,0.f); r0.y = fmaxf(r0.y,0.f); r0.z = fmaxf(r0.z,0.f); r0.w = fmaxf(r0.w,0.f);
                r1.x = fmaxf(r1.x,0.f); r1.y = fmaxf(r1.y,0.f); r1.z = fmaxf(r1.z,0.f); r1.w = fmaxf(r1.w,0.f);
            }
            *(float4*)(C + (row0 + 2*bp    )*N + 4*j) = r0;
            *(float4*)(C + (row0 + 2*bp + 1)*N + 4*j) = r1;
        }
    }
}

// ---------------- decoder LSTM + policy head ----------------
// decoder-input gates kept in REGISTERS (16 u64 per thread), not smem:
// static smem is now h_s(10KB)+c_s(9KB)+wpi(2KB) ~ 21KB < 48KB limit.
__global__ __launch_bounds__(256, 2)
void k_decoder(const int* __restrict__ lengths, const float* __restrict__ Wpi,
               const float* __restrict__ bpi, float* __restrict__ out){
    __shared__ int s_b[BC]; __shared__ int s_len[BC]; __shared__ int s_max;
    __shared__ __align__(16) float h_s[256*10];
    __shared__ __align__(16) float c_s[256*9];
    __shared__ float wpi_s[512]; __shared__ float bpi_s[2];
    const int tid = threadIdx.x;
    if (tid < BC){ int b = g_order[blockIdx.x*BC + tid]; s_b[tid] = b; s_len[tid] = lengths[b]; }
    for (int i = tid; i < 2560; i += 256) h_s[i] = 0.0f;
    if (tid < 2) bpi_s[tid] = bpi[tid];
    for (int idx = tid; idx < 512; idx += 256) wpi_s[idx] = Wpi[idx];
    __syncthreads();
    if (tid == 0){
        int m = 1;
        #pragma unroll
        for (int i = 0; i < BC; i++) m = max(m, s_len[i]);
        s_max = m;
    }

    const int j = tid;
    // per-thread decoder-input gate values: din[g][bp] packs batch lanes (2bp, 2bp+1)
    u64 din[4][4];
    #pragma unroll
    for (int g = 0; g < 4; g++){
        float v[BC];
        #pragma unroll
        for (int i = 0; i < BC; i++) v[i] = g_decin[s_b[i]*1024 + (j<<2) + g];
        #pragma unroll
        for (int bp = 0; bp < 4; bp++) din[g][bp] = pk2(v[2*bp], v[2*bp+1]);
    }
    float cr[BC];
    #pragma unroll
    for (int i = 0; i < BC; i++) cr[i] = 0.0f;
    __syncthreads();

    const int T = s_max;
    for (int t = 0; t < T; t++){
        u64 acc[4][4];
        #pragma unroll
        for (int bp = 0; bp < 4; bp++){
            acc[bp][0] = din[0][bp]; acc[bp][1] = din[1][bp];
            acc[bp][2] = din[2][bp]; acc[bp][3] = din[3][bp];
        }
        #pragma unroll 4
        for (int k = 0; k < 256; k++){
            float4 w = *(const float4*)(g_Whh2g + (k<<10) + (j<<2));
            u64 w0 = pk2(w.x,w.x), w1 = pk2(w.y,w.y), w2 = pk2(w.z,w.z), w3 = pk2(w.w,w.w);
            const float* hr = h_s + k*10;
            #pragma unroll
            for (int bp = 0; bp < 4; bp++){
                u64 hp = *(const u64*)(hr + 2*bp);
                fma2(acc[bp][0], w0, hp); fma2(acc[bp][1], w1, hp);
                fma2(acc[bp][2], w2, hp); fma2(acc[bp][3], w3, hp);
            }
        }
        __syncthreads();
        #pragma unroll
        for (int bp = 0; bp < 4; bp++){
            float2 gi = upk2(acc[bp][0]), gf = upk2(acc[bp][1]);
            float2 gg = upk2(acc[bp][2]), go = upk2(acc[bp][3]);
            int b = 2*bp;
            {
                float cn = sigf(gf.x)*cr[b] + sigf(gi.x)*tanhfast(gg.x);
                cr[b] = cn; h_s[j*10 + b] = sigf(go.x)*tanhfast(cn); c_s[j*9 + b] = cn;
            }
            b++;
            {
                float cn = sigf(gf.y)*cr[b] + sigf(gi.y)*tanhfast(gg.y);
                cr[b] = cn; h_s[j*10 + b] = sigf(go.y)*tanhfast(cn); c_s[j*9 + b] = cn;
            }
        }
        __syncthreads();
        // policy head: 16 (b,a) dot products over K=256, 16 lanes each
        {
            int p = tid >> 4, kk = tid & 15;
            int b = p >> 1, a = p & 1;
            const float* wr = wpi_s + a*256;
            float sum = 0.0f;
            #pragma unroll
            for (int q = 0; q < 16; q++){
                int k = kk + q*16;
                sum += c_s[k*9 + b] * wr[k];
            }
            sum += __shfl_xor_sync(0xffffffffu, sum, 8);
            sum += __shfl_xor_sync(0xffffffffu, sum, 4);
            sum += __shfl_xor_sync(0xffffffffu, sum, 2);
            sum += __shfl_xor_sync(0xffffffffu, sum, 1);
            if (kk == 0 && t < s_len[b])
                out[(s_b[b]*VMAXD + t)*2 + a] = tanhfast(sum + bpi_s[a]);
        }
        __syncthreads();
    }
}

__global__ void k_zero_out(float4* out){
    int i = blockIdx.x*blockDim.x + threadIdx.x;
    if (i < 131072) out[i] = make_float4(0.f, 0.f, 0.f, 0.f);
}

// ---------------- launch ----------------
extern "C" void kernel_launch(void* const* d_in, const int* in_sizes, int n_in,
                              void* d_out, int out_size){
    const float* state = (const float*)d_in[0];
    const int*   lengths = (const int*)d_in[1];
    const float* Wih1 = (const float*)d_in[2];
    const float* Whh1 = (const float*)d_in[3];
    const float* bih1 = (const float*)d_in[4];
    const float* bhh1 = (const float*)d_in[5];
    const float* W1 = (const float*)d_in[6];
    const float* b1 = (const float*)d_in[7];
    const float* W2 = (const float*)d_in[8];
    const float* b2 = (const float*)d_in[9];
    const float* W3 = (const float*)d_in[10];
    const float* b3 = (const float*)d_in[11];
    const float* W4 = (const float*)d_in[12];
    const float* b4 = (const float*)d_in[13];
    const float* Wih2 = (const float*)d_in[14];
    const float* Whh2 = (const float*)d_in[15];
    const float* bih2 = (const float*)d_in[16];
    const float* bhh2 = (const float*)d_in[17];
    const float* Wpi = (const float*)d_in[18];
    const float* bpi = (const float*)d_in[19];
    float* out = (float*)d_out;

    k_sort_init<<<1, 256>>>();
    k_sort_hist<<<8, 256>>>(lengths);
    k_sort_scan<<<1, 1>>>();
    k_sort_scatter<<<8, 256>>>(lengths);
    k_prep_gates<<<3072, 256>>>(Whh1, Wih2, Whh2);
    k_prep_small<<<68, 256>>>(Wih1, bih1, bhh1, bih2, bhh2);
    k_prep_T<<<7680, 256>>>(W1, W2, W3, W4);

    k_encoder<<<NG, 256>>>(state, lengths);

    k_rowgemm<<<NG, 256>>>(0, b1);
    k_rowgemm<<<NG, 256>>>(1, b2);
    k_rowgemm<<<NG, 256>>>(2, b3);
    k_rowgemm<<<NG, 256>>>(3, b4);
    k_rowgemm<<<NG, 256>>>(4, b1);   // bias arg ignored for layer 4 (uses g_b2c)

    k_zero_out<<<512, 256>>>((float4*)out);
    k_decoder<<<NG, 256>>>(lengths, Wpi, bpi, out);
}